// round 5
// baseline (speedup 1.0000x reference)
#include <cuda_runtime.h>
#include <cstdint>
#include <cstddef>

// Conv 3x3 s2 p1: x[32,256,64,64] * w[256,256,3,3] -> out[32,256,32,32]
// (crop mask is all-ones: python slice clamping empties every zero segment).
// Implicit GEMM with swapped operands: D[cout][m] = W[cout][k] * X[k][m],
// M-dim=cout, N-dim=spatial m, K=2304 re-enumerated k'=(kh*3+kw)*256+cin.
// Producer = cp.async.bulk (TMA/UBLKCP; base sm_90 PTX) + mbarrier expect_tx
// -> removes the LDGSTS-issue bottleneck that bound rounds 3/4.
// mma.sync.m16n8k8.tf32, tile 128x128x16, 3-stage pipeline, 2 CTAs/SM.

namespace {
constexpr int NIT = 144;                       // 2304 / 16
constexpr int XSTRIDE = 136;                   // floats per k-row (pad 8: conflict-free)
constexpr int X_STAGE_B = 16 * XSTRIDE * 4;    // 8704 B
constexpr int W_STAGE_B = 8192;                // 128 cout x 16 k x 4B
constexpr int SM_MBAR = 0;                     // 3 x 8B mbarriers
constexpr int SM_X = 64;
constexpr int SM_W = SM_X + 3 * X_STAGE_B;     // 26176
constexpr int SMEM_BYTES = SM_W + 3 * W_STAGE_B;  // 50752
}

// xS[b][cin][ihp(65)][kw(3)][32]: pre-shifted, parity-deinterleaved, tf32-rounded
// x rows; ihp=0 is an all-zero guard row (ih=-1). 128B-aligned 32-float runs.
__device__ float xS[51118080];
// wF: A-operand fragment layout, contiguous per (stage, cout-half):
// idx = (s*2+h)*2048 + (ct*2+kt)*128 + lane*4 + j
__device__ float wF[589824];

__device__ __forceinline__ uint32_t smem_u32(const void* p) {
  uint32_t a;
  asm("{ .reg .u64 t; cvta.to.shared.u64 t, %1; cvt.u32.u64 %0, t; }" : "=r"(a) : "l"(p));
  return a;
}
__device__ __forceinline__ bool elect1() {
  uint32_t p;
  asm volatile("{\n\t.reg .pred p;\n\telect.sync _|p, 0xFFFFFFFF;\n\tselp.b32 %0,1,0,p;\n\t}"
               : "=r"(p));
  return p != 0;
}
__device__ __forceinline__ void mbar_init(uint32_t a, uint32_t cnt) {
  asm volatile("mbarrier.init.shared.b64 [%0], %1;" :: "r"(a), "r"(cnt) : "memory");
}
__device__ __forceinline__ void mbar_expect_tx(uint32_t a, uint32_t tx) {
  asm volatile("mbarrier.arrive.expect_tx.shared.b64 _, [%0], %1;"
               :: "r"(a), "r"(tx) : "memory");
}
__device__ __forceinline__ void mbar_wait(uint32_t a, uint32_t parity) {
  uint32_t done;
  asm volatile(
      "{\n\t.reg .pred p;\n\t"
      "mbarrier.try_wait.parity.acquire.cta.shared::cta.b64 p, [%1], %2;\n\t"
      "selp.b32 %0, 1, 0, p;\n\t}"
      : "=r"(done) : "r"(a), "r"(parity) : "memory");
  if (!done) {
    asm volatile(
        "{\n\t.reg .pred P1;\n\t"
        "W_%=:\n\t"
        "mbarrier.try_wait.parity.acquire.cta.shared::cta.b64 P1, [%0], %1, 0x989680;\n\t"
        "@P1 bra.uni D_%=;\n\t"
        "bra.uni W_%=;\n\t"
        "D_%=:\n\t}"
        :: "r"(a), "r"(parity) : "memory");
  }
}
__device__ __forceinline__ void bulk_g2s(uint32_t dst, const void* src, uint32_t bytes,
                                         uint32_t mbar) {
  asm volatile(
      "cp.async.bulk.shared::cta.global.mbarrier::complete_tx::bytes [%0], [%1], %2, [%3];"
      :: "r"(dst), "l"(src), "r"(bytes), "r"(mbar) : "memory");
}
__device__ __forceinline__ void lds128(uint32_t* r, uint32_t a) {
  asm volatile("ld.shared.v4.b32 {%0,%1,%2,%3}, [%4];"
               : "=r"(r[0]), "=r"(r[1]), "=r"(r[2]), "=r"(r[3]) : "r"(a));
}
__device__ __forceinline__ uint32_t lds32(uint32_t a) {
  uint32_t v;
  asm volatile("ld.shared.b32 %0, [%1];" : "=r"(v) : "r"(a));
  return v;
}
__device__ __forceinline__ void mma8(float* c, const uint32_t* a, uint32_t b0, uint32_t b1) {
  asm volatile(
      "mma.sync.aligned.m16n8k8.row.col.f32.tf32.tf32.f32 "
      "{%0,%1,%2,%3}, {%4,%5,%6,%7}, {%8,%9}, {%0,%1,%2,%3};"
      : "+f"(c[0]), "+f"(c[1]), "+f"(c[2]), "+f"(c[3])
      : "r"(a[0]), "r"(a[1]), "r"(a[2]), "r"(a[3]), "r"(b0), "r"(b1));
}

// ---- prepasses ----
__global__ void zero_rows() {                  // zero the ihp=0 guard rows
  int i = blockIdx.x * 256 + threadIdx.x;      // covers 8192*96
  int bc = i / 96, j = i - bc * 96;
  xS[(size_t)bc * 6240 + j] = 0.f;             // 65*96 = 6240
}

__global__ void prep_x(const float4* __restrict__ x4) {
  int i = blockIdx.x * 256 + threadIdx.x;      // covers 8388608 float4s
  float4 v = x4[i];
  uint32_t t0, t1, t2, t3;
  asm("cvt.rna.tf32.f32 %0, %1;" : "=r"(t0) : "f"(v.x));
  asm("cvt.rna.tf32.f32 %0, %1;" : "=r"(t1) : "f"(v.y));
  asm("cvt.rna.tf32.f32 %0, %1;" : "=r"(t2) : "f"(v.z));
  asm("cvt.rna.tf32.f32 %0, %1;" : "=r"(t3) : "f"(v.w));
  int e = i << 2;
  int iw0 = e & 63;                            // 0,4,...,60
  int rid = e >> 6;                            // (b*256+cin)*64 + ih
  int bc = rid >> 6, ih = rid & 63;
  float* base = xS + (size_t)(bc * 65 + ih + 1) * 96;
  int q = iw0 >> 1;                            // even
  // kw=1 (even plane), kw=2 (odd plane)
  *(float2*)(base + 32 + q) = make_float2(__uint_as_float(t0), __uint_as_float(t2));
  *(float2*)(base + 64 + q) = make_float2(__uint_as_float(t1), __uint_as_float(t3));
  // kw=0: [0, odd[0..30]]
  base[q + 1] = __uint_as_float(t1);
  if (iw0 < 60) base[q + 2] = __uint_as_float(t3);
  if (iw0 == 0) base[0] = 0.f;
}

__global__ void prep_w(const float* __restrict__ w) {
  int i = blockIdx.x * 256 + threadIdx.x;      // covers 589824
  float v = w[i];
  uint32_t t;
  asm("cvt.rna.tf32.f32 %0, %1;" : "=r"(t) : "f"(v));
  int n = i / 2304;
  int r = i - n * 2304;
  int cin = r / 9;
  int t9 = r - cin * 9;
  int kp = t9 * 256 + cin;                     // k'
  int s = kp >> 4, kl = kp & 15;
  int kt = kl >> 3, kc = kl & 7;
  int h = n >> 7, c7 = n & 127;
  int ct = c7 >> 4, row = c7 & 15;
  int lane = (row & 7) * 4 + (kc & 3);
  int j = (row >> 3) + 2 * (kc >> 2);
  wF[(size_t)(s * 2 + h) * 2048 + (ct * 2 + kt) * 128 + lane * 4 + j] =
      __uint_as_float(t);
}

// ---- main ----
__global__ __launch_bounds__(256, 2)
void conv_main(float* __restrict__ out) {
  extern __shared__ char dsm[];
  const uint32_t sb = smem_u32(dsm);
  const int tid = threadIdx.x, lane = tid & 31, warp = tid >> 5;
  const int wc = warp & 1;                     // cout half (64) within CTA
  const int wmq = warp >> 1;                   // m quarter (32)
  const int m0 = blockIdx.x * 128;
  const int by = blockIdx.y;                   // cout half of 256
  const int n0 = by * 128;
  const int bimg = m0 >> 10;
  const int oh0 = (m0 >> 5) & 31;              // 4 output rows per tile

  float acc[4][4][4];
#pragma unroll
  for (int mi = 0; mi < 4; ++mi)
#pragma unroll
    for (int ni = 0; ni < 4; ++ni)
#pragma unroll
      for (int q = 0; q < 4; ++q) acc[mi][ni][q] = 0.f;

  if (tid == 0) {
    mbar_init(sb + SM_MBAR + 0, 1);
    mbar_init(sb + SM_MBAR + 8, 1);
    mbar_init(sb + SM_MBAR + 16, 1);
  }
  __syncthreads();

  auto issue = [&](int s2) {                   // elected thread only
    const int slot = s2 % 3;
    const uint32_t mb = sb + SM_MBAR + slot * 8;
    mbar_expect_tx(mb, 16384);                 // 8KB W + 8KB X
    bulk_g2s(sb + SM_W + slot * W_STAGE_B, wF + (size_t)(s2 * 2 + by) * 2048,
             8192, mb);
    const int tap = s2 >> 4;
    const int cinb = (s2 & 15) << 4;
    const int kh = tap / 3, kw = tap - 3 * kh;
    const float* xb = xS + (size_t)((bimg * 256 + cinb) * 65 + 2 * oh0 + kh) * 96
                      + kw * 32;
    const uint32_t xd = sb + SM_X + slot * X_STAGE_B;
#pragma unroll 4
    for (int k = 0; k < 16; ++k)
#pragma unroll
      for (int ohl = 0; ohl < 4; ++ohl)
        bulk_g2s(xd + k * 544 + ohl * 128, xb + (size_t)k * 6240 + ohl * 192,
                 128, mb);
  };

  if (warp == 0 && elect1()) { issue(0); issue(1); }

  for (int s = 0; s < NIT; ++s) {
    const int slot = s % 3;
    mbar_wait(sb + SM_MBAR + slot * 8, (s / 3) & 1);

    // A-frags (W): 8x LDS.128 from fragment layout
    uint32_t aw[4][2][4];
    const uint32_t wbase = sb + SM_W + slot * W_STAGE_B + lane * 16;
#pragma unroll
    for (int mi = 0; mi < 4; ++mi)
#pragma unroll
      for (int kt = 0; kt < 2; ++kt)
        lds128(aw[mi][kt], wbase + ((wc * 4 + mi) * 2 + kt) * 512);

    // B-frags (X): scalar LDS, conflict-free (stride 136 floats)
    const uint32_t xbase = sb + SM_X + slot * X_STAGE_B + (lane & 3) * 544
                           + (wmq * 32 + (lane >> 2)) * 4;
#pragma unroll
    for (int ni = 0; ni < 4; ++ni) {
      const uint32_t a0 = xbase + ni * 32;
      uint32_t b0 = lds32(a0);
      uint32_t b1 = lds32(a0 + 4 * 544);
      uint32_t b2 = lds32(a0 + 8 * 544);
      uint32_t b3 = lds32(a0 + 12 * 544);
#pragma unroll
      for (int mi = 0; mi < 4; ++mi) {
        mma8(acc[mi][ni], aw[mi][0], b0, b1);
        mma8(acc[mi][ni], aw[mi][1], b2, b3);
      }
    }
    __syncthreads();                           // slot fully consumed by all warps
    if (s + 2 < NIT && warp == 0 && elect1()) issue(s + 2);
  }

  // Epilogue: D[cout][m]; m contiguous in out -> STG.64 pairs
  const int l4 = lane >> 2, lm = lane & 3;
  const int spb = m0 & 1023;
#pragma unroll
  for (int mi = 0; mi < 4; ++mi) {
    const int cr = n0 + wc * 64 + mi * 16 + l4;
#pragma unroll
    for (int ni = 0; ni < 4; ++ni) {
      const int mcol = wmq * 32 + ni * 8 + 2 * lm;
      float* o = out + ((size_t)(bimg * 256 + cr)) * 1024 + spb + mcol;
      *(float2*)o = make_float2(acc[mi][ni][0], acc[mi][ni][1]);
      *(float2*)(o + 8 * 1024) = make_float2(acc[mi][ni][2], acc[mi][ni][3]);
    }
  }
}

extern "C" void kernel_launch(void* const* d_in, const int* in_sizes, int n_in,
                              void* d_out, int out_size) {
  (void)out_size;
  const float* x = (const float*)d_in[0];
  const float* w = (const float*)d_in[1];
  if (n_in >= 2 && in_sizes[0] < in_sizes[1]) {  // defensive ordering by size
    x = (const float*)d_in[1];
    w = (const float*)d_in[0];
  }
  cudaFuncSetAttribute(conv_main, cudaFuncAttributeMaxDynamicSharedMemorySize,
                       SMEM_BYTES);
  zero_rows<<<3072, 256>>>();
  prep_x<<<32768, 256>>>((const float4*)x);
  prep_w<<<2304, 256>>>(w);
  dim3 grid(256, 2);
  conv_main<<<grid, 256, SMEM_BYTES>>>((float*)d_out);
}

// round 6
// speedup vs baseline: 1.5381x; 1.5381x over previous
#include <cuda_runtime.h>
#include <cstdint>
#include <cstddef>

// Conv 3x3 s2 p1: x[32,256,64,64] * w[256,256,3,3] -> out[32,256,32,32]
// (crop mask is all-ones: python slice clamping empties every zero segment).
// Implicit GEMM, swapped operands: D[cout][m] = W[cout][k] * X[k][m],
// K re-enumerated k'=(kh*3+kw)*256+cin. X staged via xS (pre-shifted,
// parity-deinterleaved, zero guard row) so the producer is 4x 16B cp.async
// per thread per stage with ZERO predicates. mma.sync m16n8k8 tf32,
// tile 128x128x16, 3-stage cp.async pipeline, 2 CTAs/SM.

namespace {
constexpr int NIT = 144;                       // 2304 / 16
constexpr int X_STAGE_B = 16 * 544;            // 8704 B (k-row stride 544B)
constexpr int W_STAGE_B = 8192;                // 128 cout x 16 k x 4B
constexpr int SM_X = 0;
constexpr int SM_W = 3 * X_STAGE_B;            // 26112
constexpr int SMEM_BYTES = SM_W + 3 * W_STAGE_B;  // 50688
}

// xS[b][cin][ihp(65)][kw(3)][32]: pre-shifted, parity-deinterleaved, tf32-rounded
// rows; ihp=0 is an all-zero guard row (ih=-1). Every (k, oh) run = 128B aligned.
__device__ float xS[51118080];
// wF: A-operand fragment layout, contiguous 8KB per (stage, cout-half):
// idx = (s*2+h)*2048 + (ct*2+kt)*128 + lane*4 + j
__device__ float wF[589824];

__device__ __forceinline__ uint32_t smem_u32(const void* p) {
  uint32_t a;
  asm("{ .reg .u64 t; cvta.to.shared.u64 t, %1; cvt.u32.u64 %0, t; }" : "=r"(a) : "l"(p));
  return a;
}
__device__ __forceinline__ void lds128(uint32_t* r, uint32_t a) {
  asm volatile("ld.shared.v4.b32 {%0,%1,%2,%3}, [%4];"
               : "=r"(r[0]), "=r"(r[1]), "=r"(r[2]), "=r"(r[3]) : "r"(a));
}
__device__ __forceinline__ uint32_t lds32(uint32_t a) {
  uint32_t v;
  asm volatile("ld.shared.b32 %0, [%1];" : "=r"(v) : "r"(a));
  return v;
}
__device__ __forceinline__ void cpa16(uint32_t dst, const void* src) {
  asm volatile("cp.async.cg.shared.global [%0], [%1], 16;\n" :: "r"(dst), "l"(src));
}
__device__ __forceinline__ void mma8(float* c, const uint32_t* a, uint32_t b0, uint32_t b1) {
  asm volatile(
      "mma.sync.aligned.m16n8k8.row.col.f32.tf32.tf32.f32 "
      "{%0,%1,%2,%3}, {%4,%5,%6,%7}, {%8,%9}, {%0,%1,%2,%3};"
      : "+f"(c[0]), "+f"(c[1]), "+f"(c[2]), "+f"(c[3])
      : "r"(a[0]), "r"(a[1]), "r"(a[2]), "r"(a[3]), "r"(b0), "r"(b1));
}

// ---- prepasses ----
__global__ void zero_rows() {                  // zero the ihp=0 guard rows
  int i = blockIdx.x * 256 + threadIdx.x;      // covers 8192*96
  int bc = i / 96, j = i - bc * 96;
  xS[(size_t)bc * 6240 + j] = 0.f;             // 65*96 = 6240 floats per (b,cin)
}

__global__ void prep_x(const float4* __restrict__ x4) {
  int i = blockIdx.x * 256 + threadIdx.x;      // covers 8388608 float4s
  float4 v = x4[i];
  uint32_t t0, t1, t2, t3;
  asm("cvt.rna.tf32.f32 %0, %1;" : "=r"(t0) : "f"(v.x));
  asm("cvt.rna.tf32.f32 %0, %1;" : "=r"(t1) : "f"(v.y));
  asm("cvt.rna.tf32.f32 %0, %1;" : "=r"(t2) : "f"(v.z));
  asm("cvt.rna.tf32.f32 %0, %1;" : "=r"(t3) : "f"(v.w));
  int e = i << 2;
  int iw0 = e & 63;                            // 0,4,...,60
  int rid = e >> 6;                            // (b*256+cin)*64 + ih
  int bc = rid >> 6, ih = rid & 63;
  float* base = xS + (size_t)(bc * 65 + ih + 1) * 96;
  int q = iw0 >> 1;
  // kw=1 plane: even iw; kw=2 plane: odd iw
  *(float2*)(base + 32 + q) = make_float2(__uint_as_float(t0), __uint_as_float(t2));
  *(float2*)(base + 64 + q) = make_float2(__uint_as_float(t1), __uint_as_float(t3));
  // kw=0 plane: [0, odd shifted right]
  base[q + 1] = __uint_as_float(t1);
  if (iw0 < 60) base[q + 2] = __uint_as_float(t3);
  if (iw0 == 0) base[0] = 0.f;
}

__global__ void prep_w(const float* __restrict__ w) {
  int i = blockIdx.x * 256 + threadIdx.x;      // covers 589824
  float v = w[i];
  uint32_t t;
  asm("cvt.rna.tf32.f32 %0, %1;" : "=r"(t) : "f"(v));
  int n = i / 2304;
  int r = i - n * 2304;
  int cin = r / 9;
  int t9 = r - cin * 9;
  int kp = t9 * 256 + cin;                     // k'
  int s = kp >> 4, kl = kp & 15;
  int kt = kl >> 3, kc = kl & 7;
  int h = n >> 7, c7 = n & 127;
  int ct = c7 >> 4, row = c7 & 15;
  int lane = (row & 7) * 4 + (kc & 3);
  int j = (row >> 3) + 2 * (kc >> 2);
  wF[(size_t)(s * 2 + h) * 2048 + (ct * 2 + kt) * 128 + lane * 4 + j] =
      __uint_as_float(t);
}

// ---- main ----
__global__ __launch_bounds__(256, 2)
void conv_main(float* __restrict__ out) {
  extern __shared__ char dsm[];
  const uint32_t sb = smem_u32(dsm);
  const int tid = threadIdx.x, lane = tid & 31, warp = tid >> 5;
  const int wc = warp & 1;                     // cout half (64) within CTA
  const int wmq = warp >> 1;                   // m quarter (32)
  const int m0 = blockIdx.x * 128;
  const int by = blockIdx.y;                   // cout half of 256
  const int n0 = by * 128;
  const int bimg = m0 >> 10;
  const int oh0 = (m0 >> 5) & 31;              // 4 output rows per tile

  float acc[4][4][4];
#pragma unroll
  for (int mi = 0; mi < 4; ++mi)
#pragma unroll
    for (int ni = 0; ni < 4; ++ni)
#pragma unroll
      for (int q = 0; q < 4; ++q) acc[mi][ni][q] = 0.f;

  // Producer decomposition: X tile = 512 x 16B chunks; thread t owns chunks
  // {t, t+256}. chunk c: k=c>>5, ohl=(c>>3)&3, seg=c&7.
  const int c0 = tid, c1 = tid + 256;
  const int k0c = c0 >> 5, oh0c = (c0 >> 3) & 3, sg0 = c0 & 7;
  const int k1c = c1 >> 5, oh1c = (c1 >> 3) & 3, sg1 = c1 & 7;
  const float* xR = xS + ((size_t)(bimg * 256) * 65 + 2 * oh0) * 96;
  const float* wR = wF + (size_t)by * 2048 + tid * 8;

  auto load_stage = [&](int s, int slot) {
    const int tap = s >> 4;
    const int cinb = (s & 15) << 4;
    const int kh = tap / 3, kw = tap - 3 * kh;
    const float* xb = xR + (size_t)(cinb * 65 + kh) * 96 + kw * 32;
    const uint32_t xd = sb + SM_X + slot * X_STAGE_B;
    cpa16(xd + k0c * 544 + oh0c * 128 + sg0 * 16,
          xb + (size_t)k0c * 6240 + oh0c * 192 + sg0 * 4);
    cpa16(xd + k1c * 544 + oh1c * 128 + sg1 * 16,
          xb + (size_t)k1c * 6240 + oh1c * 192 + sg1 * 4);
    const float* ws = wR + (size_t)s * 4096;
    const uint32_t wd = sb + SM_W + slot * W_STAGE_B + tid * 32;
    cpa16(wd, ws);
    cpa16(wd + 16, ws + 4);
    asm volatile("cp.async.commit_group;\n");
  };

  load_stage(0, 0);
  load_stage(1, 1);

  int buf = 0, buf2 = 2;                       // buf=s%3, buf2=(s+2)%3
  for (int s = 0; s < NIT; ++s) {
    asm volatile("cp.async.wait_group 1;\n" ::: "memory");
    __syncthreads();
    if (s + 2 < NIT) load_stage(s + 2, buf2);

    // A-frags (W): 8x LDS.128 from fragment layout
    uint32_t aw[4][2][4];
    const uint32_t wbase = sb + SM_W + buf * W_STAGE_B + lane * 16;
#pragma unroll
    for (int mi = 0; mi < 4; ++mi)
#pragma unroll
      for (int kt = 0; kt < 2; ++kt)
        lds128(aw[mi][kt], wbase + ((wc * 4 + mi) * 2 + kt) * 512);

    // B-frags (X): scalar LDS, conflict-free (k-row stride 544B)
    const uint32_t xbase = sb + SM_X + buf * X_STAGE_B + (lane & 3) * 544
                           + (wmq * 32 + (lane >> 2)) * 4;
#pragma unroll
    for (int ni = 0; ni < 4; ++ni) {
      const uint32_t a0 = xbase + ni * 32;
      uint32_t b0 = lds32(a0);
      uint32_t b1 = lds32(a0 + 4 * 544);
      uint32_t b2 = lds32(a0 + 8 * 544);
      uint32_t b3 = lds32(a0 + 12 * 544);
#pragma unroll
      for (int mi = 0; mi < 4; ++mi) {
        mma8(acc[mi][ni], aw[mi][0], b0, b1);
        mma8(acc[mi][ni], aw[mi][1], b2, b3);
      }
    }
    buf = (buf == 2) ? 0 : buf + 1;
    buf2 = (buf2 == 2) ? 0 : buf2 + 1;
  }

  // Epilogue: D[cout][m]; m contiguous in out -> STG.64 pairs
  const int l4 = lane >> 2, lm = lane & 3;
  const int spb = m0 & 1023;
#pragma unroll
  for (int mi = 0; mi < 4; ++mi) {
    const int cr = n0 + wc * 64 + mi * 16 + l4;
#pragma unroll
    for (int ni = 0; ni < 4; ++ni) {
      const int mcol = wmq * 32 + ni * 8 + 2 * lm;
      float* o = out + ((size_t)(bimg * 256 + cr)) * 1024 + spb + mcol;
      *(float2*)o = make_float2(acc[mi][ni][0], acc[mi][ni][1]);
      *(float2*)(o + 8 * 1024) = make_float2(acc[mi][ni][2], acc[mi][ni][3]);
    }
  }
}

extern "C" void kernel_launch(void* const* d_in, const int* in_sizes, int n_in,
                              void* d_out, int out_size) {
  (void)out_size;
  const float* x = (const float*)d_in[0];
  const float* w = (const float*)d_in[1];
  if (n_in >= 2 && in_sizes[0] < in_sizes[1]) {  // defensive ordering by size
    x = (const float*)d_in[1];
    w = (const float*)d_in[0];
  }
  cudaFuncSetAttribute(conv_main, cudaFuncAttributeMaxDynamicSharedMemorySize,
                       SMEM_BYTES);
  zero_rows<<<3072, 256>>>();
  prep_x<<<32768, 256>>>((const float4*)x);
  prep_w<<<2304, 256>>>(w);
  dim3 grid(256, 2);
  conv_main<<<grid, 256, SMEM_BYTES>>>((float*)d_out);
}

// round 7
// speedup vs baseline: 1.6066x; 1.0446x over previous
#include <cuda_runtime.h>
#include <cstdint>
#include <cstddef>

// Conv 3x3 s2 p1: x[32,256,64,64] * w[256,256,3,3] -> out[32,256,32,32]
// (crop mask is all-ones: python slice clamping empties every zero segment).
// Implicit GEMM, swapped operands: D[cout][m] = W[cout][k] * X[k][m],
// K re-enumerated k'=(kh*3+kw)*256+cin. X staged via xS (pre-shifted,
// parity-deinterleaved, zero guard row): producer = 8x 16B cp.async per
// thread per 32-K stage, ZERO predicates. mma.sync m16n8k8 tf32,
// tile 128x128x32, 3-stage pipeline, 2 CTAs/SM, cout-pairs adjacent in grid
// for L2 X sharing.

namespace {
constexpr int NIT = 72;                        // 2304 / 32
constexpr int X_STAGE_B = 32 * 544;            // 17408 B (k-row stride 544B)
constexpr int W_STAGE_B = 16384;               // 128 cout x 32 k x 4B
constexpr int SM_X = 0;
constexpr int SM_W = 3 * X_STAGE_B;            // 52224
constexpr int SMEM_BYTES = SM_W + 3 * W_STAGE_B;  // 101376 (x2 CTAs = 203KB/SM)
}

// xS[b][cin][ihp(65)][kw(3)][32]: pre-shifted, parity-deinterleaved, tf32-rounded
// rows; ihp=0 is an all-zero guard row (ih=-1). Every (k, oh) run = 128B aligned.
__device__ float xS[51118080];
// wF: A-operand fragment layout, contiguous 8KB per (s16, cout-half):
// idx = (s16*2+h)*2048 + (ct*2+kt)*128 + lane*4 + j
__device__ float wF[589824];

__device__ __forceinline__ uint32_t smem_u32(const void* p) {
  uint32_t a;
  asm("{ .reg .u64 t; cvta.to.shared.u64 t, %1; cvt.u32.u64 %0, t; }" : "=r"(a) : "l"(p));
  return a;
}
__device__ __forceinline__ void lds128(uint32_t* r, uint32_t a) {
  asm volatile("ld.shared.v4.b32 {%0,%1,%2,%3}, [%4];"
               : "=r"(r[0]), "=r"(r[1]), "=r"(r[2]), "=r"(r[3]) : "r"(a));
}
__device__ __forceinline__ uint32_t lds32(uint32_t a) {
  uint32_t v;
  asm volatile("ld.shared.b32 %0, [%1];" : "=r"(v) : "r"(a));
  return v;
}
__device__ __forceinline__ void cpa16(uint32_t dst, const void* src) {
  asm volatile("cp.async.cg.shared.global [%0], [%1], 16;\n" :: "r"(dst), "l"(src));
}
__device__ __forceinline__ void mma8(float* c, const uint32_t* a, uint32_t b0, uint32_t b1) {
  asm volatile(
      "mma.sync.aligned.m16n8k8.row.col.f32.tf32.tf32.f32 "
      "{%0,%1,%2,%3}, {%4,%5,%6,%7}, {%8,%9}, {%0,%1,%2,%3};"
      : "+f"(c[0]), "+f"(c[1]), "+f"(c[2]), "+f"(c[3])
      : "r"(a[0]), "r"(a[1]), "r"(a[2]), "r"(a[3]), "r"(b0), "r"(b1));
}

// ---- prepasses ----
__global__ void zero_rows() {                  // zero the ihp=0 guard rows
  int i = blockIdx.x * 256 + threadIdx.x;      // covers 8192*96
  int bc = i / 96, j = i - bc * 96;
  xS[(size_t)bc * 6240 + j] = 0.f;             // 65*96 = 6240 floats per (b,cin)
}

__global__ void prep_x(const float4* __restrict__ x4) {
  int i = blockIdx.x * 256 + threadIdx.x;      // covers 8388608 float4s
  float4 v = x4[i];
  uint32_t t0, t1, t2, t3;
  asm("cvt.rna.tf32.f32 %0, %1;" : "=r"(t0) : "f"(v.x));
  asm("cvt.rna.tf32.f32 %0, %1;" : "=r"(t1) : "f"(v.y));
  asm("cvt.rna.tf32.f32 %0, %1;" : "=r"(t2) : "f"(v.z));
  asm("cvt.rna.tf32.f32 %0, %1;" : "=r"(t3) : "f"(v.w));
  int e = i << 2;
  int iw0 = e & 63;                            // 0,4,...,60
  int rid = e >> 6;                            // (b*256+cin)*64 + ih
  int bc = rid >> 6, ih = rid & 63;
  float* base = xS + (size_t)(bc * 65 + ih + 1) * 96;
  int q = iw0 >> 1;
  // kw=1 plane: even iw; kw=2 plane: odd iw
  *(float2*)(base + 32 + q) = make_float2(__uint_as_float(t0), __uint_as_float(t2));
  *(float2*)(base + 64 + q) = make_float2(__uint_as_float(t1), __uint_as_float(t3));
  // kw=0 plane: [0, odd shifted right]
  base[q + 1] = __uint_as_float(t1);
  if (iw0 < 60) base[q + 2] = __uint_as_float(t3);
  if (iw0 == 0) base[0] = 0.f;
}

__global__ void prep_w(const float* __restrict__ w) {
  int i = blockIdx.x * 256 + threadIdx.x;      // covers 589824
  float v = w[i];
  uint32_t t;
  asm("cvt.rna.tf32.f32 %0, %1;" : "=r"(t) : "f"(v));
  int n = i / 2304;
  int r = i - n * 2304;
  int cin = r / 9;
  int t9 = r - cin * 9;
  int kp = t9 * 256 + cin;                     // k'
  int s16 = kp >> 4, kl = kp & 15;
  int kt = kl >> 3, kc = kl & 7;
  int h = n >> 7, c7 = n & 127;
  int ct = c7 >> 4, row = c7 & 15;
  int lane = (row & 7) * 4 + (kc & 3);
  int j = (row >> 3) + 2 * (kc >> 2);
  wF[(size_t)(s16 * 2 + h) * 2048 + (ct * 2 + kt) * 128 + lane * 4 + j] =
      __uint_as_float(t);
}

// ---- main ----
__global__ __launch_bounds__(256, 2)
void conv_main(float* __restrict__ out) {
  extern __shared__ char dsm[];
  const uint32_t sb = smem_u32(dsm);
  const int tid = threadIdx.x, lane = tid & 31, warp = tid >> 5;
  const int wc = warp & 1;                     // cout half (64) within CTA
  const int wmq = warp >> 1;                   // m quarter (32)
  const int n0 = blockIdx.x * 128;             // cout half of 256 (FAST grid dim)
  const int by = blockIdx.x;
  const int m0 = blockIdx.y * 128;
  const int bimg = m0 >> 10;
  const int oh0 = (m0 >> 5) & 31;              // 4 output rows per tile

  float acc[4][4][4];
#pragma unroll
  for (int mi = 0; mi < 4; ++mi)
#pragma unroll
    for (int ni = 0; ni < 4; ++ni)
#pragma unroll
      for (int q = 0; q < 4; ++q) acc[mi][ni][q] = 0.f;

  // Producer: X data chunks d = tid + 256*j (j=0..3), d in [0,1024):
  // k = d>>5, ohl = (d>>3)&3, sg = d&7. No predicates, no pad chunks.
  const float* xR = xS + ((size_t)(bimg * 256) * 65 + 2 * oh0) * 96;
  const float* wR = wF + (size_t)by * 2048 + tid * 8;

  auto load_stage = [&](int s, int slot) {
    const int tap = s >> 3;                    // 32 k per stage, 8 stages per tap
    const int cinb = (s & 7) << 5;
    const int kh = tap / 3, kw = tap - 3 * kh;
    const float* xb = xR + (size_t)(cinb * 65 + kh) * 96 + kw * 32;
    const uint32_t xd = sb + SM_X + slot * X_STAGE_B;
#pragma unroll
    for (int j = 0; j < 4; ++j) {
      const int d = tid + 256 * j;
      const int k = d >> 5, ohl = (d >> 3) & 3, sg = d & 7;
      cpa16(xd + k * 544 + ohl * 128 + sg * 16,
            xb + (size_t)k * 6240 + ohl * 192 + sg * 4);
    }
    // W: two 8KB blocks (s16 = 2s, 2s+1), 2 chunks per thread per block
    const uint32_t wd = sb + SM_W + slot * W_STAGE_B;
#pragma unroll
    for (int blk = 0; blk < 2; ++blk) {
      const float* ws = wR + (size_t)(2 * s + blk) * 4096;
      const uint32_t wdd = wd + blk * 8192 + tid * 32;
      cpa16(wdd, ws);
      cpa16(wdd + 16, ws + 4);
    }
    asm volatile("cp.async.commit_group;\n");
  };

  load_stage(0, 0);
  load_stage(1, 1);

  int buf = 0, buf2 = 2;                       // buf=s%3, buf2=(s+2)%3
  for (int s = 0; s < NIT; ++s) {
    asm volatile("cp.async.wait_group 1;\n" ::: "memory");
    __syncthreads();
    if (s + 2 < NIT) load_stage(s + 2, buf2);

    const uint32_t wbase = sb + SM_W + buf * W_STAGE_B + lane * 16;
    const uint32_t xbase = sb + SM_X + buf * X_STAGE_B + (lane & 3) * 544
                           + (wmq * 32 + (lane >> 2)) * 4;
    // 4 k-chunks of 8; loads of chunk j+1 overlap mma of chunk j via ptxas
#pragma unroll
    for (int j = 0; j < 4; ++j) {
      uint32_t aw[4][4];
      const uint32_t wj = wbase + (j >> 1) * 8192 + (j & 1) * 512;
#pragma unroll
      for (int mi = 0; mi < 4; ++mi)
        lds128(aw[mi], wj + (wc * 4 + mi) * 1024);
      const uint32_t xj = xbase + j * 8 * 544;
#pragma unroll
      for (int ni = 0; ni < 4; ++ni) {
        const uint32_t a0 = xj + ni * 32;
        uint32_t b0 = lds32(a0);
        uint32_t b1 = lds32(a0 + 4 * 544);
#pragma unroll
        for (int mi = 0; mi < 4; ++mi)
          mma8(acc[mi][ni], aw[mi], b0, b1);
      }
    }
    buf = (buf == 2) ? 0 : buf + 1;
    buf2 = (buf2 == 2) ? 0 : buf2 + 1;
  }

  // Epilogue: D[cout][m]; m contiguous in out -> STG.64 pairs
  const int l4 = lane >> 2, lm = lane & 3;
  const int spb = m0 & 1023;
#pragma unroll
  for (int mi = 0; mi < 4; ++mi) {
    const int cr = n0 + wc * 64 + mi * 16 + l4;
#pragma unroll
    for (int ni = 0; ni < 4; ++ni) {
      const int mcol = wmq * 32 + ni * 8 + 2 * lm;
      float* o = out + ((size_t)(bimg * 256 + cr)) * 1024 + spb + mcol;
      *(float2*)o = make_float2(acc[mi][ni][0], acc[mi][ni][1]);
      *(float2*)(o + 8 * 1024) = make_float2(acc[mi][ni][2], acc[mi][ni][3]);
    }
  }
}

extern "C" void kernel_launch(void* const* d_in, const int* in_sizes, int n_in,
                              void* d_out, int out_size) {
  (void)out_size;
  const float* x = (const float*)d_in[0];
  const float* w = (const float*)d_in[1];
  if (n_in >= 2 && in_sizes[0] < in_sizes[1]) {  // defensive ordering by size
    x = (const float*)d_in[1];
    w = (const float*)d_in[0];
  }
  cudaFuncSetAttribute(conv_main, cudaFuncAttributeMaxDynamicSharedMemorySize,
                       SMEM_BYTES);
  zero_rows<<<3072, 256>>>();
  prep_x<<<32768, 256>>>((const float4*)x);
  prep_w<<<2304, 256>>>(w);
  dim3 grid(2, 256);                           // cout-half fastest: L2 X sharing
  conv_main<<<grid, 256, SMEM_BYTES>>>((float*)d_out);
}

// round 8
// speedup vs baseline: 2.6441x; 1.6458x over previous
#include <cuda_runtime.h>
#include <cuda_fp16.h>
#include <cstdint>
#include <cstddef>

// Conv 3x3 s2 p1: x[32,256,64,64] * w[256,256,3,3] -> out[32,256,32,32]
// (crop mask is all-ones: python slice clamping empties every zero segment).
// Implicit GEMM, swapped operands: D[cout][m] = W[cout][k] * X[k][m],
// K re-enumerated k'=(kh*3+kw)*256+cin. FP16 datapath (same 10-bit mantissa
// as tf32; fp32 accumulate): mma.sync m16n8k16.f32.f16.f16.f32.
// W = A-operand in prepass fragment layout (lds128); X = B-operand, k-major
// m-contiguous smem, fragments via ldmatrix.x4.trans. Producer = 4x 16B
// cp.async/thread/stage, zero predicates. Tile 128x128x32, 3-stage pipeline,
// 2 CTAs/SM, cout-pairs adjacent in grid for L2 X sharing.

namespace {
constexpr int NIT = 72;                        // 2304 / 32
constexpr int XROW = 272;                      // bytes per k-row (256 data + 16 pad)
constexpr int X_STAGE_B = 32 * XROW;           // 8704
constexpr int W_STAGE_B = 8192;                // 128 cout x 32 k x 2B
constexpr int SM_X = 0;
constexpr int SM_W = 3 * X_STAGE_B;            // 26112
constexpr int SMEM_BYTES = SM_W + 3 * W_STAGE_B;  // 50688 (x2 CTAs ok)
}

// xH[b][cin][ihp(65)][kw(3)][32] halves: pre-shifted, parity-deinterleaved,
// fp16-rounded rows; ihp=0 is an all-zero guard row (ih=-1).
__device__ __half xH[51118080];
// wH: A-operand m16n8k16 fragment layout, 8KB per (stage s, cout-half by):
// halfidx = (s*2+by)*4096 + (j*8+ct)*256 + lane*8 + reg*2 + hf
__device__ __half wH[589824];

__device__ __forceinline__ uint32_t smem_u32(const void* p) {
  uint32_t a;
  asm("{ .reg .u64 t; cvta.to.shared.u64 t, %1; cvt.u32.u64 %0, t; }" : "=r"(a) : "l"(p));
  return a;
}
__device__ __forceinline__ void lds128(uint32_t* r, uint32_t a) {
  asm volatile("ld.shared.v4.b32 {%0,%1,%2,%3}, [%4];"
               : "=r"(r[0]), "=r"(r[1]), "=r"(r[2]), "=r"(r[3]) : "r"(a));
}
__device__ __forceinline__ void ldsm4t(uint32_t* r, uint32_t a) {
  asm volatile("ldmatrix.sync.aligned.m8n8.x4.trans.shared.b16 {%0,%1,%2,%3}, [%4];"
               : "=r"(r[0]), "=r"(r[1]), "=r"(r[2]), "=r"(r[3]) : "r"(a));
}
__device__ __forceinline__ void cpa16(uint32_t dst, const void* src) {
  asm volatile("cp.async.cg.shared.global [%0], [%1], 16;\n" :: "r"(dst), "l"(src));
}
__device__ __forceinline__ void mma16(float* c, const uint32_t* a, uint32_t b0, uint32_t b1) {
  asm volatile(
      "mma.sync.aligned.m16n8k16.row.col.f32.f16.f16.f32 "
      "{%0,%1,%2,%3}, {%4,%5,%6,%7}, {%8,%9}, {%0,%1,%2,%3};"
      : "+f"(c[0]), "+f"(c[1]), "+f"(c[2]), "+f"(c[3])
      : "r"(a[0]), "r"(a[1]), "r"(a[2]), "r"(a[3]), "r"(b0), "r"(b1));
}

// ---- prepasses ----
__global__ void zero_rows() {                  // zero the ihp=0 guard rows
  int i = blockIdx.x * 256 + threadIdx.x;      // covers 8192*48 u32 words
  int bc = i / 48, j = i - bc * 48;
  ((uint32_t*)xH)[(size_t)bc * 3120 + j] = 0u; // 6240 halves per (b,cin)
}

__global__ void prep_x(const float4* __restrict__ x4) {
  int i = blockIdx.x * 256 + threadIdx.x;      // covers 8388608 float4s
  float4 v = x4[i];
  __half h0 = __float2half_rn(v.x), h1 = __float2half_rn(v.y);
  __half h2 = __float2half_rn(v.z), h3 = __float2half_rn(v.w);
  int e = i << 2;
  int iw0 = e & 63;                            // 0,4,...,60
  int rid = e >> 6;                            // (b*256+cin)*64 + ih
  int bc = rid >> 6, ih = rid & 63;
  __half* base = xH + (size_t)(bc * 65 + ih + 1) * 96;
  int q = iw0 >> 1;                            // even
  // kw=1 plane: even iw; kw=2 plane: odd iw (q even -> 4B aligned)
  *(__half2*)(base + 32 + q) = __halves2half2(h0, h2);
  *(__half2*)(base + 64 + q) = __halves2half2(h1, h3);
  // kw=0 plane: [0, odd shifted right]
  base[q + 1] = h1;
  if (iw0 < 60) base[q + 2] = h3;
  if (iw0 == 0) base[0] = __float2half_rn(0.f);
}

__global__ void prep_w(const float* __restrict__ w) {
  int i = blockIdx.x * 256 + threadIdx.x;      // covers 589824
  __half hv = __float2half_rn(w[i]);
  int n = i / 2304;
  int r = i - n * 2304;
  int cin = r / 9;
  int t9 = r - cin * 9;
  int kp = t9 * 256 + cin;                     // k'
  int s = kp >> 5, k32 = kp & 31;
  int j = k32 >> 4, kk = k32 & 15;
  int by = n >> 7, c7 = n & 127;
  int ct = c7 >> 4, row16 = c7 & 15;           // A-row within 16-tile
  int g = row16 & 7, rlo = row16 >> 3;
  int reg = (kk >> 3) * 2 + rlo;               // a0..a3
  int tg = (kk & 7) >> 1, hf = kk & 1;
  int lane = g * 4 + tg;
  wH[(size_t)(s * 2 + by) * 4096 + (j * 8 + ct) * 256 + lane * 8 + reg * 2 + hf] = hv;
}

// ---- main ----
__global__ __launch_bounds__(256, 2)
void conv_main(float* __restrict__ out) {
  extern __shared__ char dsm[];
  const uint32_t sb = smem_u32(dsm);
  const int tid = threadIdx.x, lane = tid & 31, warp = tid >> 5;
  const int wc = warp & 1;                     // cout half (64) within CTA
  const int wmq = warp >> 1;                   // m quarter (32)
  const int n0 = blockIdx.x * 128;             // cout half of 256 (fast grid dim)
  const int by = blockIdx.x;
  const int m0 = blockIdx.y * 128;
  const int bimg = m0 >> 10;
  const int oh0 = (m0 >> 5) & 31;              // 4 output rows per tile

  float acc[4][4][4];
#pragma unroll
  for (int mi = 0; mi < 4; ++mi)
#pragma unroll
    for (int ni = 0; ni < 4; ++ni)
#pragma unroll
      for (int q = 0; q < 4; ++q) acc[mi][ni][q] = 0.f;

  // ldmatrix address components (thread-invariant)
  const int quad = lane >> 3;
  const int rowb = (quad & 1) * 8 + (lane & 7);          // k within 16
  const int ncolb = wmq * 32 + (quad >> 1) * 8;          // m column base
  const __half* xR = xH + ((size_t)(bimg * 256) * 65 + 2 * oh0) * 96;

  auto load_stage = [&](int s, int slot) {
    const int tap = s >> 3;                    // 8 stages per (kh,kw) tap
    const int cinb = (s & 7) << 5;
    const int kh = tap / 3, kw = tap - 3 * kh;
    const __half* xb = xR + (size_t)(cinb * 65 + kh) * 96 + kw * 32;
    const uint32_t xd = sb + SM_X + slot * X_STAGE_B;
    // X: 512 x 16B chunks / 256 threads = 2 each; c: k=c>>4, ohl=(c>>2)&3, sg=c&3
#pragma unroll
    for (int jj = 0; jj < 2; ++jj) {
      const int c = tid + 256 * jj;
      const int k = c >> 4, ohl = (c >> 2) & 3, sg = c & 3;
      cpa16(xd + k * XROW + ohl * 64 + sg * 16,
            xb + (size_t)k * 6240 + ohl * 192 + sg * 8);
    }
    // W: 8KB fragment block for (s, by); 2 chunks per thread
    const __half* ws = wH + (size_t)(s * 2 + by) * 4096 + tid * 16;
    const uint32_t wd = sb + SM_W + slot * W_STAGE_B + tid * 32;
    cpa16(wd, ws);
    cpa16(wd + 16, ws + 8);
    asm volatile("cp.async.commit_group;\n");
  };

  load_stage(0, 0);
  load_stage(1, 1);

  int buf = 0, buf2 = 2;                       // buf=s%3, buf2=(s+2)%3
  for (int s = 0; s < NIT; ++s) {
    asm volatile("cp.async.wait_group 1;\n" ::: "memory");
    __syncthreads();
    if (s + 2 < NIT) load_stage(s + 2, buf2);

    const uint32_t wbase = sb + SM_W + buf * W_STAGE_B + lane * 16;
    const uint32_t xbase = sb + SM_X + buf * X_STAGE_B + rowb * XROW + ncolb * 2;
#pragma unroll
    for (int j = 0; j < 2; ++j) {              // two k16 chunks
      uint32_t aw[4][4];
#pragma unroll
      for (int mi = 0; mi < 4; ++mi)
        lds128(aw[mi], wbase + (j * 8 + wc * 4 + mi) * 512);
      uint32_t bx[2][4];
      const uint32_t xj = xbase + j * 16 * XROW;
      ldsm4t(bx[0], xj);                       // ni 0,1
      ldsm4t(bx[1], xj + 32);                  // ni 2,3 (m +16 halves)
#pragma unroll
      for (int ni = 0; ni < 4; ++ni) {
        const uint32_t b0 = bx[ni >> 1][(ni & 1) * 2];
        const uint32_t b1 = bx[ni >> 1][(ni & 1) * 2 + 1];
#pragma unroll
        for (int mi = 0; mi < 4; ++mi)
          mma16(acc[mi][ni], aw[mi], b0, b1);
      }
    }
    buf = (buf == 2) ? 0 : buf + 1;
    buf2 = (buf2 == 2) ? 0 : buf2 + 1;
  }

  // Epilogue: D[cout][m]; m contiguous in out -> STG.64 pairs
  const int l4 = lane >> 2, lm = lane & 3;
  const int spb = m0 & 1023;
#pragma unroll
  for (int mi = 0; mi < 4; ++mi) {
    const int cr = n0 + wc * 64 + mi * 16 + l4;
#pragma unroll
    for (int ni = 0; ni < 4; ++ni) {
      const int mcol = wmq * 32 + ni * 8 + 2 * lm;
      float* o = out + ((size_t)(bimg * 256 + cr)) * 1024 + spb + mcol;
      *(float2*)o = make_float2(acc[mi][ni][0], acc[mi][ni][1]);
      *(float2*)(o + 8 * 1024) = make_float2(acc[mi][ni][2], acc[mi][ni][3]);
    }
  }
}

extern "C" void kernel_launch(void* const* d_in, const int* in_sizes, int n_in,
                              void* d_out, int out_size) {
  (void)out_size;
  const float* x = (const float*)d_in[0];
  const float* w = (const float*)d_in[1];
  if (n_in >= 2 && in_sizes[0] < in_sizes[1]) {  // defensive ordering by size
    x = (const float*)d_in[1];
    w = (const float*)d_in[0];
  }
  cudaFuncSetAttribute(conv_main, cudaFuncAttributeMaxDynamicSharedMemorySize,
                       SMEM_BYTES);
  zero_rows<<<1536, 256>>>();
  prep_x<<<32768, 256>>>((const float4*)x);
  prep_w<<<2304, 256>>>(w);
  dim3 grid(2, 256);                           // cout-half fastest: L2 X sharing
  conv_main<<<grid, 256, SMEM_BYTES>>>((float*)d_out);
}